// round 6
// baseline (speedup 1.0000x reference)
#include <cuda_runtime.h>
#include <cuda_bf16.h>
#include <cstdint>
#include <math.h>

// ============================================================================
// GGRU cell, B=16384, H=1024  (sm_103 base target: mma.sync tf32 + cp.async)
//   reset = sigmoid(prev @ Wur[:,H:2H] + inp[:,2H:3H])   (GEMM1)
//   X     = inp[:,:H] * reset
//   p     = X @ U                                        (GEMM2)
//   out   = m*(tanh(p + inp[:,:H]) + prev + 1) + (1-m)*prev
// (update gate cancels: u + (1-u) == 1)
// ============================================================================

#define HDIM 1024
#define BROWS 16384
#define MT 128
#define NT 128
#define KC 32            // K per stage
#define NSTAGE_ITERS 32  // HDIM / KC
#define STAGES 3
#define THREADS 256

#define ASTAGE_BYTES (MT * KC * 4)         // 16384
#define STAGE_BYTES  (2 * ASTAGE_BYTES)    // 32768
#define SMEM_TOTAL   (STAGES * STAGE_BYTES) // 98304

// Scratch (device globals: allocation-free per harness rules)
__device__ float g_Wt[(size_t)HDIM * HDIM];   // Wur[:,H:2H]^T  -> [n][k]
__device__ float g_Ut[(size_t)HDIM * HDIM];   // U^T            -> [n][k]
__device__ float g_X [(size_t)BROWS * HDIM];  // state_inp * reset

// ---------------------------------------------------------------------------
__device__ __forceinline__ uint32_t smem_u32(const void* p) {
    uint32_t a;
    asm("{ .reg .u64 t; cvta.to.shared.u64 t, %1; cvt.u32.u64 %0, t; }"
        : "=r"(a) : "l"(p));
    return a;
}

#define CP_ASYNC16(saddr, gaddr) \
    asm volatile("cp.async.cg.shared.global [%0], [%1], 16;" \
        :: "r"(saddr), "l"(gaddr))
#define CP_COMMIT() asm volatile("cp.async.commit_group;" ::: "memory")
#define CP_WAIT1()  asm volatile("cp.async.wait_group 1;" ::: "memory")

#define LDSM_X4(r0, r1, r2, r3, addr) \
    asm volatile("ldmatrix.sync.aligned.m8n8.x4.shared.b16 {%0,%1,%2,%3}, [%4];" \
        : "=r"(r0), "=r"(r1), "=r"(r2), "=r"(r3) : "r"(addr))

#define CVT_TF32(x) asm("cvt.rna.tf32.f32 %0, %0;" : "+r"(x))

#define MMA_TF32(c, a, b) \
    asm volatile("mma.sync.aligned.m16n8k8.row.col.f32.tf32.tf32.f32 " \
        "{%0,%1,%2,%3}, {%4,%5,%6,%7}, {%8,%9}, {%0,%1,%2,%3};" \
        : "+f"((c)[0]), "+f"((c)[1]), "+f"((c)[2]), "+f"((c)[3]) \
        : "r"((a)[0]), "r"((a)[1]), "r"((a)[2]), "r"((a)[3]), \
          "r"((b)[0]), "r"((b)[1]))

__device__ __forceinline__ float sigmoidf_(float x) {
    return 1.0f / (1.0f + __expf(-x));
}

// ---------------------------------------------------------------------------
// Weight transpose: dst[n][k] = src[k][col_off + n].  1024x1024.
// ---------------------------------------------------------------------------
__global__ void transpose_kernel(const float* __restrict__ src, int src_ld,
                                 int col_off, int which) {
    __shared__ float tile[32][33];
    float* dst = which ? g_Ut : g_Wt;
    int n0 = blockIdx.x * 32, k0 = blockIdx.y * 32;
    int tx = threadIdx.x;
    for (int dy = threadIdx.y; dy < 32; dy += 8)
        tile[dy][tx] = src[(size_t)(k0 + dy) * src_ld + col_off + n0 + tx];
    __syncthreads();
    for (int dy = threadIdx.y; dy < 32; dy += 8)
        dst[(size_t)(n0 + dy) * HDIM + k0 + tx] = tile[tx][dy];
}

// ---------------------------------------------------------------------------
// Fused tf32 GEMM (mma.sync) + epilogue.
//   A: [M rows][K], row-major.  B: [N][K] row-major (pre-transposed weights).
//   EPI=0: X = s * sigmoid(D + gate_r)          (A=prev,  B=g_Wt)
//   EPI=1: out = m*(tanh(D+s)+prev+1)+(1-m)*prev (A=g_X,  B=g_Ut)
// ---------------------------------------------------------------------------
template <int EPI>
__global__ void __launch_bounds__(THREADS, 2)
gemm_kernel(const float* __restrict__ Aparam, const float* __restrict__ inp,
            const float* __restrict__ prev, const float* __restrict__ mask,
            float* __restrict__ outp) {
    extern __shared__ char smem[];
    const uint32_t smem_base = smem_u32(smem);
    const int tid = threadIdx.x;
    const int lane = tid & 31;
    const int wid = tid >> 5;
    const int warpM = wid >> 1;         // 0..3  (32 rows each)
    const int warpN = wid & 1;          // 0..1  (64 cols each)

    const float* Aptr = (EPI == 0) ? Aparam : g_X;
    const float* Bt   = (EPI == 0) ? g_Wt : g_Ut;

    const size_t mbase = (size_t)blockIdx.y * MT;
    const int nbase = blockIdx.x * NT;
    const float* Ag = Aptr + mbase * HDIM;
    const float* Bg = Bt + (size_t)nbase * HDIM;

    // ---- staging offsets (each thread copies 4x16B of A and 4x16B of B) ----
    uint32_t sA[4], sB[4];
    size_t gA[4], gB[4];
#pragma unroll
    for (int i = 0; i < 4; i++) {
        int cid = tid + i * 256;       // 0..1023
        int row = cid >> 3;            // 0..127
        int c = cid & 7;               // 16B chunk in 128B row
        uint32_t so = (uint32_t)(row * 128 + ((c ^ (row & 7)) << 4));
        size_t go = (size_t)row * HDIM + c * 4;
        sA[i] = so; gA[i] = go;
        sB[i] = so; gB[i] = go;
    }

    // ---- ldmatrix per-lane base offsets ----
    const int q = lane >> 3;
    const int l7 = lane & 7;
    // A: quads -> (rows {0-7,8-15}, kchunk {lo,lo,hi,hi})
    const uint32_t a_row_off = (uint32_t)((warpM * 32 + (q & 1) * 8 + l7) * 128);
    const int a_csel = q >> 1;
    // B: quads -> (rows {0-7,0-7,8-15,8-15}, kchunk {lo,hi,lo,hi})
    const uint32_t b_row_off = (uint32_t)((warpN * 64 + (q >> 1) * 8 + l7) * 128);
    const int b_csel = q & 1;

    float acc[2][8][4];
#pragma unroll
    for (int mt = 0; mt < 2; mt++)
#pragma unroll
        for (int nt = 0; nt < 8; nt++)
#pragma unroll
            for (int j = 0; j < 4; j++) acc[mt][nt][j] = 0.0f;

    // ---- prologue: issue stages 0,1 ----
#pragma unroll
    for (int s = 0; s < 2; s++) {
        uint32_t sb = smem_base + s * STAGE_BYTES;
        size_t kb = (size_t)(s * KC);
#pragma unroll
        for (int i = 0; i < 4; i++) CP_ASYNC16(sb + sA[i], Ag + gA[i] + kb);
#pragma unroll
        for (int i = 0; i < 4; i++)
            CP_ASYNC16(sb + ASTAGE_BYTES + sB[i], Bg + gB[i] + kb);
        CP_COMMIT();
    }

    // ---- main loop ----
    for (int ksi = 0; ksi < NSTAGE_ITERS; ksi++) {
        CP_WAIT1();
        __syncthreads();

        // issue stage ksi+2
        if (ksi + 2 < NSTAGE_ITERS) {
            int s = ksi + 2;
            uint32_t sb = smem_base + (s % STAGES) * STAGE_BYTES;
            size_t kb = (size_t)(s * KC);
#pragma unroll
            for (int i = 0; i < 4; i++) CP_ASYNC16(sb + sA[i], Ag + gA[i] + kb);
#pragma unroll
            for (int i = 0; i < 4; i++)
                CP_ASYNC16(sb + ASTAGE_BYTES + sB[i], Bg + gB[i] + kb);
        }
        CP_COMMIT();

        // compute stage ksi
        uint32_t Asm = smem_base + (ksi % STAGES) * STAGE_BYTES;
        uint32_t Bsm = Asm + ASTAGE_BYTES;
#pragma unroll
        for (int kl = 0; kl < 4; kl++) {   // 4 k-steps of 8
            uint32_t a[2][4];
#pragma unroll
            for (int mt = 0; mt < 2; mt++) {
                uint32_t addr = Asm + a_row_off + mt * 2048 +
                                (uint32_t)((((2 * kl + a_csel) ^ l7)) << 4);
                LDSM_X4(a[mt][0], a[mt][1], a[mt][2], a[mt][3], addr);
            }
#pragma unroll
            for (int mt = 0; mt < 2; mt++) {
                CVT_TF32(a[mt][0]); CVT_TF32(a[mt][1]);
                CVT_TF32(a[mt][2]); CVT_TF32(a[mt][3]);
            }
#pragma unroll
            for (int half = 0; half < 2; half++) {
                uint32_t b[4][2];
#pragma unroll
                for (int p = 0; p < 2; p++) {
                    uint32_t addr = Bsm + b_row_off + (half * 2 + p) * 2048 +
                                    (uint32_t)((((2 * kl + b_csel) ^ l7)) << 4);
                    LDSM_X4(b[2 * p][0], b[2 * p][1],
                            b[2 * p + 1][0], b[2 * p + 1][1], addr);
                }
#pragma unroll
                for (int t = 0; t < 4; t++) { CVT_TF32(b[t][0]); CVT_TF32(b[t][1]); }
#pragma unroll
                for (int mt = 0; mt < 2; mt++)
#pragma unroll
                    for (int t = 0; t < 4; t++)
                        MMA_TF32(acc[mt][half * 4 + t], a[mt], b[t]);
            }
        }
    }

    // ---- epilogue (accumulators in registers) ----
    const int g = lane >> 2, tq = lane & 3;
#pragma unroll
    for (int mt = 0; mt < 2; mt++) {
#pragma unroll
        for (int h = 0; h < 2; h++) {
            size_t m = mbase + warpM * 32 + mt * 16 + h * 8 + g;
            const float* srow = inp + m * (size_t)(3 * HDIM);
            if (EPI == 0) {
                float* xr = g_X + m * (size_t)HDIM;
#pragma unroll
                for (int nt = 0; nt < 8; nt++) {
                    int n = nbase + warpN * 64 + nt * 8 + tq * 2;
                    float2 s = *(const float2*)(srow + n);
                    float2 gi = *(const float2*)(srow + 2 * HDIM + n);
                    float d0 = acc[mt][nt][h * 2];
                    float d1 = acc[mt][nt][h * 2 + 1];
                    float2 o;
                    o.x = s.x * sigmoidf_(d0 + gi.x);
                    o.y = s.y * sigmoidf_(d1 + gi.y);
                    *(float2*)(xr + n) = o;
                }
            } else {
                float mk = mask[m], omk = 1.0f - mk;
                const float* prow = prev + m * (size_t)HDIM;
                float* orow = outp + m * (size_t)HDIM;
#pragma unroll
                for (int nt = 0; nt < 8; nt++) {
                    int n = nbase + warpN * 64 + nt * 8 + tq * 2;
                    float2 s = *(const float2*)(srow + n);
                    float2 pv = *(const float2*)(prow + n);
                    float d0 = acc[mt][nt][h * 2];
                    float d1 = acc[mt][nt][h * 2 + 1];
                    float t0 = tanhf(d0 + s.x);
                    float t1 = tanhf(d1 + s.y);
                    float2 o;
                    o.x = mk * (t0 + pv.x + 1.0f) + omk * pv.x;
                    o.y = mk * (t1 + pv.y + 1.0f) + omk * pv.y;
                    *(float2*)(orow + n) = o;
                }
            }
        }
    }
}

// ---------------------------------------------------------------------------
extern "C" void kernel_launch(void* const* d_in, const int* in_sizes, int n_in,
                              void* d_out, int out_size) {
    const float* inp  = (const float*)d_in[0];
    const float* prev = (const float*)d_in[1];
    const float* mask = (const float*)d_in[2];
    const float* Wur  = (const float*)d_in[3];
    const float* U    = (const float*)d_in[4];
    float* out = (float*)d_out;
    (void)in_sizes; (void)n_in; (void)out_size;

    cudaFuncSetAttribute(gemm_kernel<0>,
                         cudaFuncAttributeMaxDynamicSharedMemorySize, SMEM_TOTAL);
    cudaFuncSetAttribute(gemm_kernel<1>,
                         cudaFuncAttributeMaxDynamicSharedMemorySize, SMEM_TOTAL);

    dim3 tb(32, 8);
    transpose_kernel<<<dim3(32, 32), tb>>>(Wur, 2 * HDIM, HDIM, 0);  // g_Wt
    transpose_kernel<<<dim3(32, 32), tb>>>(U, HDIM, 0, 1);           // g_Ut

    dim3 grid(HDIM / NT, BROWS / MT);  // (8, 128)
    gemm_kernel<0><<<grid, THREADS, SMEM_TOTAL>>>(prev, inp, prev, mask, out);
    gemm_kernel<1><<<grid, THREADS, SMEM_TOTAL>>>(prev, inp, prev, mask, out);
}

// round 10
// speedup vs baseline: 1.7223x; 1.7223x over previous
#include <cuda_runtime.h>
#include <cuda_fp16.h>
#include <cstdint>
#include <math.h>

// ============================================================================
// GGRU cell, B=16384, H=1024  (sm_103 base target: mma.sync f16 + cp.async)
//   reset = sigmoid(prev @ Wur[:,H:2H] + inp[:,2H:3H])   (GEMM1)
//   X     = inp[:,:H] * reset
//   p     = X @ U                                        (GEMM2)
//   out   = m*(tanh(p + inp[:,:H]) + prev + 1) + (1-m)*prev
// (update gate cancels: u + (1-u) == 1)
// fp16 operands (same 11-bit mantissa as tf32), fp32 accumulate.
// ============================================================================

#define HDIM 1024
#define BROWS 16384
#define MT 128
#define NT 128
#define KC 64             // K per stage (one 128B row of halves)
#define NSTAGE_ITERS 16   // HDIM / KC
#define STAGES 3
#define THREADS 256

#define ASTAGE_BYTES (MT * 128)            // 16384 (128 rows x 128B)
#define STAGE_BYTES  (2 * ASTAGE_BYTES)    // 32768
#define SMEM_TOTAL   (STAGES * STAGE_BYTES) // 98304

// Scratch (device globals: allocation-free per harness rules)
__device__ __half g_Wh[(size_t)HDIM * HDIM];   // Wur[:,H:2H]^T -> [n][k], fp16
__device__ __half g_Uh[(size_t)HDIM * HDIM];   // U^T           -> [n][k], fp16
__device__ __half g_Ph[(size_t)BROWS * HDIM];  // fp16(prev)
__device__ __half g_Xh[(size_t)BROWS * HDIM];  // fp16(state_inp * reset)

// ---------------------------------------------------------------------------
__device__ __forceinline__ uint32_t smem_u32(const void* p) {
    uint32_t a;
    asm("{ .reg .u64 t; cvta.to.shared.u64 t, %1; cvt.u32.u64 %0, t; }"
        : "=r"(a) : "l"(p));
    return a;
}

#define CP_ASYNC16(saddr, gaddr) \
    asm volatile("cp.async.cg.shared.global [%0], [%1], 16;" \
        :: "r"(saddr), "l"(gaddr))
#define CP_COMMIT() asm volatile("cp.async.commit_group;" ::: "memory")
#define CP_WAIT1()  asm volatile("cp.async.wait_group 1;" ::: "memory")

#define LDSM_X4(r0, r1, r2, r3, addr) \
    asm volatile("ldmatrix.sync.aligned.m8n8.x4.shared.b16 {%0,%1,%2,%3}, [%4];" \
        : "=r"(r0), "=r"(r1), "=r"(r2), "=r"(r3) : "r"(addr))

#define MMA_F16(c, a, b0_, b1_) \
    asm volatile("mma.sync.aligned.m16n8k16.row.col.f32.f16.f16.f32 " \
        "{%0,%1,%2,%3}, {%4,%5,%6,%7}, {%8,%9}, {%0,%1,%2,%3};" \
        : "+f"((c)[0]), "+f"((c)[1]), "+f"((c)[2]), "+f"((c)[3]) \
        : "r"((a)[0]), "r"((a)[1]), "r"((a)[2]), "r"((a)[3]), \
          "r"(b0_), "r"(b1_))

__device__ __forceinline__ float sigmoidf_(float x) {
    return 1.0f / (1.0f + __expf(-x));
}

// ---------------------------------------------------------------------------
// Weight transpose + fp16 round: dst[n][k] = fp16(src[k][col_off + n]).
// ---------------------------------------------------------------------------
__global__ void transpose_kernel(const float* __restrict__ src, int src_ld,
                                 int col_off, int which) {
    __shared__ float tile[32][33];
    __half* dst = which ? g_Uh : g_Wh;
    int n0 = blockIdx.x * 32, k0 = blockIdx.y * 32;
    int tx = threadIdx.x;
    for (int dy = threadIdx.y; dy < 32; dy += 8)
        tile[dy][tx] = src[(size_t)(k0 + dy) * src_ld + col_off + n0 + tx];
    __syncthreads();
    for (int dy = threadIdx.y; dy < 32; dy += 8)
        dst[(size_t)(n0 + dy) * HDIM + k0 + tx] = __float2half_rn(tile[tx][dy]);
}

// fp32 -> fp16 bulk convert (prev -> g_Ph)
__global__ void tohalf_kernel(const float* __restrict__ src) {
    int stride = gridDim.x * blockDim.x;
    for (int i = blockIdx.x * blockDim.x + threadIdx.x;
         i < BROWS * HDIM / 4; i += stride) {
        float4 v = ((const float4*)src)[i];
        __half2* d = (__half2*)g_Ph;
        d[2 * i]     = __floats2half2_rn(v.x, v.y);
        d[2 * i + 1] = __floats2half2_rn(v.z, v.w);
    }
}

// ---------------------------------------------------------------------------
// Fused fp16 GEMM (mma.sync m16n8k16) + epilogue.
//   A: [M][K] row-major fp16.  B: [N][K] row-major fp16 (pre-transposed).
//   EPI=0: Xh = fp16(s * sigmoid(D + gate_r))        (A=g_Ph, B=g_Wh)
//   EPI=1: out = m*(tanh(D+s)+prev+1)+(1-m)*prev     (A=g_Xh, B=g_Uh)
// ---------------------------------------------------------------------------
template <int EPI>
__global__ void __launch_bounds__(THREADS, 2)
gemm_kernel(const float* __restrict__ inp, const float* __restrict__ prev,
            const float* __restrict__ mask, float* __restrict__ outp) {
    extern __shared__ char smem[];
    const uint32_t smem_base = smem_u32(smem);
    const int tid = threadIdx.x;
    const int lane = tid & 31;
    const int wid = tid >> 5;
    const int warpM = wid >> 1;   // 0..3 (32 rows each)
    const int warpN = wid & 1;    // 0..1 (64 cols each)

    const __half* Ag0 = (EPI == 0) ? g_Ph : g_Xh;
    const __half* Bg0 = (EPI == 0) ? g_Wh : g_Uh;

    const size_t mbase = (size_t)blockIdx.y * MT;
    const int nbase = blockIdx.x * NT;
    const __half* Ag = Ag0 + mbase * HDIM;
    const __half* Bg = Bg0 + (size_t)nbase * HDIM;

    // ---- staging offsets: each thread copies 4x16B of A and 4x16B of B ----
    uint32_t sO[4];
    size_t gO[4];
#pragma unroll
    for (int i = 0; i < 4; i++) {
        int cid = tid + i * 256;       // 0..1023
        int row = cid >> 3;            // 0..127
        int c = cid & 7;               // 16B chunk within 128B row
        sO[i] = (uint32_t)(row * 128 + ((c ^ (row & 7)) << 4));
        gO[i] = (size_t)row * HDIM + c * 8;   // halves
    }

    // ---- ldmatrix per-lane invariants ----
    const int q = lane >> 3;
    const int l7 = lane & 7;
    // A quads: row +{0,8} by q&1, k-chunk +{0,1} by q>>1
    uint32_t a_row[2];
#pragma unroll
    for (int mt = 0; mt < 2; mt++)
        a_row[mt] = (uint32_t)((warpM * 32 + mt * 16 + (q & 1) * 8 + l7) * 128);
    // B quads: n-tile +{0,1} by q>>1, k-chunk +{0,1} by q&1
    uint32_t b_row[4];
#pragma unroll
    for (int p = 0; p < 4; p++)
        b_row[p] = (uint32_t)((warpN * 64 + (2 * p + (q >> 1)) * 8 + l7) * 128);
    uint32_t xa[4], xb[4];
#pragma unroll
    for (int kl = 0; kl < 4; kl++) {
        xa[kl] = (uint32_t)(((2 * kl + (q >> 1)) ^ l7) << 4);
        xb[kl] = (uint32_t)(((2 * kl + (q & 1)) ^ l7) << 4);
    }

    float acc[2][8][4];
#pragma unroll
    for (int mt = 0; mt < 2; mt++)
#pragma unroll
        for (int nt = 0; nt < 8; nt++)
#pragma unroll
            for (int j = 0; j < 4; j++) acc[mt][nt][j] = 0.0f;

    // ---- prologue: issue stages 0,1 ----
#pragma unroll
    for (int s = 0; s < 2; s++) {
        uint32_t sb = smem_base + s * STAGE_BYTES;
        size_t kb = (size_t)(s * KC);
#pragma unroll
        for (int i = 0; i < 4; i++) CP_ASYNC16(sb + sO[i], Ag + gO[i] + kb);
#pragma unroll
        for (int i = 0; i < 4; i++)
            CP_ASYNC16(sb + ASTAGE_BYTES + sO[i], Bg + gO[i] + kb);
        CP_COMMIT();
    }

    // ---- main loop ----
    for (int ksi = 0; ksi < NSTAGE_ITERS; ksi++) {
        CP_WAIT1();
        __syncthreads();

        if (ksi + 2 < NSTAGE_ITERS) {
            int s = ksi + 2;
            uint32_t sb = smem_base + (s % STAGES) * STAGE_BYTES;
            size_t kb = (size_t)(s * KC);
#pragma unroll
            for (int i = 0; i < 4; i++) CP_ASYNC16(sb + sO[i], Ag + gO[i] + kb);
#pragma unroll
            for (int i = 0; i < 4; i++)
                CP_ASYNC16(sb + ASTAGE_BYTES + sO[i], Bg + gO[i] + kb);
        }
        CP_COMMIT();

        uint32_t Asm = smem_base + (ksi % STAGES) * STAGE_BYTES;
        uint32_t Bsm = Asm + ASTAGE_BYTES;
#pragma unroll
        for (int kl = 0; kl < 4; kl++) {   // 4 k-steps of 16
            uint32_t a[2][4];
#pragma unroll
            for (int mt = 0; mt < 2; mt++)
                LDSM_X4(a[mt][0], a[mt][1], a[mt][2], a[mt][3],
                        Asm + a_row[mt] + xa[kl]);
#pragma unroll
            for (int p = 0; p < 4; p++) {  // two n8-tiles per ldmatrix.x4
                uint32_t b0, b1, b2, b3;
                LDSM_X4(b0, b1, b2, b3, Bsm + b_row[p] + xb[kl]);
#pragma unroll
                for (int mt = 0; mt < 2; mt++) {
                    MMA_F16(acc[mt][2 * p], a[mt], b0, b1);
                    MMA_F16(acc[mt][2 * p + 1], a[mt], b2, b3);
                }
            }
        }
    }

    // ---- epilogue (accumulators in registers) ----
    const int g = lane >> 2, tq = lane & 3;
#pragma unroll
    for (int mt = 0; mt < 2; mt++) {
#pragma unroll
        for (int h = 0; h < 2; h++) {
            size_t m = mbase + warpM * 32 + mt * 16 + h * 8 + g;
            const float* srow = inp + m * (size_t)(3 * HDIM);
            if (EPI == 0) {
                __half* xr = g_Xh + m * (size_t)HDIM;
#pragma unroll
                for (int nt = 0; nt < 8; nt++) {
                    int n = nbase + warpN * 64 + nt * 8 + tq * 2;
                    float2 s = *(const float2*)(srow + n);
                    float2 gi = *(const float2*)(srow + 2 * HDIM + n);
                    float d0 = acc[mt][nt][h * 2];
                    float d1 = acc[mt][nt][h * 2 + 1];
                    float ox = s.x * sigmoidf_(d0 + gi.x);
                    float oy = s.y * sigmoidf_(d1 + gi.y);
                    *(__half2*)(xr + n) = __floats2half2_rn(ox, oy);
                }
            } else {
                float mk = mask[m], omk = 1.0f - mk;
                const float* prow = prev + m * (size_t)HDIM;
                float* orow = outp + m * (size_t)HDIM;
#pragma unroll
                for (int nt = 0; nt < 8; nt++) {
                    int n = nbase + warpN * 64 + nt * 8 + tq * 2;
                    float2 s = *(const float2*)(srow + n);
                    float2 pv = *(const float2*)(prow + n);
                    float d0 = acc[mt][nt][h * 2];
                    float d1 = acc[mt][nt][h * 2 + 1];
                    float t0 = tanhf(d0 + s.x);
                    float t1 = tanhf(d1 + s.y);
                    float2 o;
                    o.x = mk * (t0 + pv.x + 1.0f) + omk * pv.x;
                    o.y = mk * (t1 + pv.y + 1.0f) + omk * pv.y;
                    *(float2*)(orow + n) = o;
                }
            }
        }
    }
}

// ---------------------------------------------------------------------------
extern "C" void kernel_launch(void* const* d_in, const int* in_sizes, int n_in,
                              void* d_out, int out_size) {
    const float* inp  = (const float*)d_in[0];
    const float* prev = (const float*)d_in[1];
    const float* mask = (const float*)d_in[2];
    const float* Wur  = (const float*)d_in[3];
    const float* U    = (const float*)d_in[4];
    float* out = (float*)d_out;
    (void)in_sizes; (void)n_in; (void)out_size;

    cudaFuncSetAttribute(gemm_kernel<0>,
                         cudaFuncAttributeMaxDynamicSharedMemorySize, SMEM_TOTAL);
    cudaFuncSetAttribute(gemm_kernel<1>,
                         cudaFuncAttributeMaxDynamicSharedMemorySize, SMEM_TOTAL);

    tohalf_kernel<<<4096, 256>>>(prev);
    dim3 tb(32, 8);
    transpose_kernel<<<dim3(32, 32), tb>>>(Wur, 2 * HDIM, HDIM, 0);  // g_Wh
    transpose_kernel<<<dim3(32, 32), tb>>>(U, HDIM, 0, 1);           // g_Uh

    dim3 grid(HDIM / NT, BROWS / MT);  // (8, 128)
    gemm_kernel<0><<<grid, THREADS, SMEM_TOTAL>>>(inp, prev, mask, out);
    gemm_kernel<1><<<grid, THREADS, SMEM_TOTAL>>>(inp, prev, mask, out);
}